// round 11
// baseline (speedup 1.0000x reference)
#include <cuda_runtime.h>
#include <cuda_fp16.h>
#include <cstdint>
#include <math.h>

// Problem constants (fixed shapes)
#define CN      100000
#define CE      1600000
#define CNFEAT  512
#define CNLABEL 64
#define CNHID   256
#define CHID2   512

// ---------------- scratch (device globals) ----------------------------------
__device__ float  g_t   [(size_t)CN * CNHID];
__device__ __half g_h_hi[(size_t)CN * CNHID];
__device__ __half g_h_lo[(size_t)CN * CNHID];
__device__ __half g_m_hi[(size_t)CN * CHID2];
__device__ __half g_m_lo[(size_t)CN * CHID2];
__device__ __half g_x_hi[(size_t)CN * CNFEAT];
__device__ __half g_x_lo[(size_t)CN * CNFEAT];
__device__ __half g_w0t_hi[256 * 512], g_w0t_lo[256 * 512];
__device__ __half g_w1t_hi[256 * 256], g_w1t_lo[256 * 256];
__device__ __half g_w2t_hi[256 * 256], g_w2t_lo[256 * 256];
__device__ __half g_wm0t_hi[512 * 256], g_wm0t_lo[512 * 256];
__device__ __half g_wm1t_hi[64 * 512],  g_wm1t_lo[64 * 512];
__device__ float  g_dinv[CN];
__device__ int    g_cnt[CN];
__device__ int    g_rowptr[CN + 1];
__device__ int    g_cursor[CN];
__device__ int    g_src[CE];
__device__ float  g_w[CE];
__device__ int    g_lab[CN];

// ---------------- CSR build --------------------------------------------------
__global__ void k_zero_cnt(int n) {
    int i = blockIdx.x * blockDim.x + threadIdx.x;
    if (i < n) g_cnt[i] = 0;
}
__global__ void k_count(const int* __restrict__ adj, int E) {
    int e = blockIdx.x * blockDim.x + threadIdx.x;
    if (e >= E) return;
    atomicAdd(&g_cnt[adj[E + e]], 1);
}
__global__ void k_scan(int n, int E) {
    __shared__ int bs[1024];
    int tid = threadIdx.x;
    int chunk = (n + 1023) / 1024;
    int lo = tid * chunk;
    int hi = lo + chunk; if (hi > n) hi = n; if (lo > n) lo = n;
    int s = 0;
    for (int i = lo; i < hi; i++) s += g_cnt[i];
    int mysum = s;
    bs[tid] = s;
    __syncthreads();
    for (int d = 1; d < 1024; d <<= 1) {
        int v = (tid >= d) ? bs[tid - d] : 0;
        __syncthreads();
        bs[tid] += v;
        __syncthreads();
    }
    int off = bs[tid] - mysum;
    for (int i = lo; i < hi; i++) {
        g_rowptr[i] = off;
        g_cursor[i] = off;
        off += g_cnt[i];
    }
    if (tid == 1023) g_rowptr[n] = E;
}
__global__ void k_dinv(int n) {
    int i = blockIdx.x * blockDim.x + threadIdx.x;
    if (i < n) g_dinv[i] = rsqrtf((float)g_cnt[i] + 2.0f);
}
__global__ void k_fill(const int* __restrict__ adj, int E) {
    int e = blockIdx.x * blockDim.x + threadIdx.x;
    if (e >= E) return;
    int src = adj[e];
    int dst = adj[E + e];
    int pos = atomicAdd(&g_cursor[dst], 1);
    g_src[pos] = src;
    g_w[pos] = g_dinv[src] * g_dinv[dst];
}

// ---------------- labels ------------------------------------------------------
__global__ void k_lab_init(int n) {
    int i = blockIdx.x * blockDim.x + threadIdx.x;
    if (i < n) g_lab[i] = -1;
}
__global__ void k_lab_set(const int* __restrict__ idxl, const int* __restrict__ y, int L) {
    int t = blockIdx.x * blockDim.x + threadIdx.x;
    if (t >= L) return;
    int node = idxl[t];
    g_lab[node] = y[node];
}
__global__ void k_lab_add(const float* __restrict__ W0, int n) {
    int gt = blockIdx.x * blockDim.x + threadIdx.x;
    int warp = gt >> 5, lane = gt & 31;
    if (warp >= n) return;
    int lab = g_lab[warp];
    if (lab < 0) return;
    const float* wrow = W0 + (size_t)(CNFEAT + lab) * CNHID;
    float* trow = g_t + (size_t)warp * CNHID;
#pragma unroll
    for (int k = 0; k < CNHID / 32; k++)
        trow[k * 32 + lane] += wrow[k * 32 + lane];
}

// ---------------- split helpers ------------------------------------------------
__device__ __forceinline__ void split1(float v, __half& h, __half& l) {
    h = __float2half_rn(v);
    l = __float2half_rn(v - __half2float(h));
}

__global__ void k_split(const float* __restrict__ X, __half* __restrict__ H,
                        __half* __restrict__ L, long long nq) {
    long long i = (long long)blockIdx.x * blockDim.x + threadIdx.x;
    if (i >= nq) return;
    float4 v = ((const float4*)X)[i];
    __half2 h0 = __floats2half2_rn(v.x, v.y), h1 = __floats2half2_rn(v.z, v.w);
    float2 f0 = __half22float2(h0), f1 = __half22float2(h1);
    __half2 l0 = __floats2half2_rn(v.x - f0.x, v.y - f0.y);
    __half2 l1 = __floats2half2_rn(v.z - f1.x, v.w - f1.y);
    ((__half2*)H)[2 * i] = h0; ((__half2*)H)[2 * i + 1] = h1;
    ((__half2*)L)[2 * i] = l0; ((__half2*)L)[2 * i + 1] = l1;
}

__global__ void k_wt(const float* __restrict__ W, __half* __restrict__ TH,
                     __half* __restrict__ TL, int K, int N) {
    int idx = blockIdx.x * blockDim.x + threadIdx.x;
    if (idx >= N * K) return;
    int n = idx / K, k = idx % K;
    float v = W[(size_t)k * N + n];
    __half h, l;
    split1(v, h, l);
    TH[idx] = h;
    TL[idx] = l;
}

// ---------------- fused CSR aggregation (4-edge unroll) ------------------------
__global__ void __launch_bounds__(256)
k_agg_csr(const float* __restrict__ t, __half* __restrict__ Oh, __half* __restrict__ Ol,
          const float* __restrict__ bias, int n) {
    int warp = (blockIdx.x * blockDim.x + threadIdx.x) >> 5;
    int lane = threadIdx.x & 31;
    if (warp >= n) return;
    int beg = g_rowptr[warp];
    int end = g_rowptr[warp + 1];
    const float4* ti = (const float4*)(t + (size_t)warp * CNHID);
    const float4* bi = (const float4*)bias;
    float d = g_dinv[warp];
    float sw = 2.0f * d * d;

    float4 a0 = bi[lane], a1 = bi[32 + lane];
    float4 s0 = ti[lane], s1 = ti[32 + lane];
    a0.x += sw * s0.x; a0.y += sw * s0.y; a0.z += sw * s0.z; a0.w += sw * s0.w;
    a1.x += sw * s1.x; a1.y += sw * s1.y; a1.z += sw * s1.z; a1.w += sw * s1.w;

    int e = beg;
    for (; e + 3 < end; e += 4) {
        int   si[4];
        float wi[4];
#pragma unroll
        for (int j = 0; j < 4; j++) { si[j] = g_src[e + j]; wi[j] = g_w[e + j]; }
        float4 v0[4], v1[4];
#pragma unroll
        for (int j = 0; j < 4; j++) {
            const float4* tp = (const float4*)(t + (size_t)si[j] * CNHID);
            v0[j] = tp[lane];
            v1[j] = tp[32 + lane];
        }
#pragma unroll
        for (int j = 0; j < 4; j++) {
            a0.x = fmaf(wi[j], v0[j].x, a0.x); a0.y = fmaf(wi[j], v0[j].y, a0.y);
            a0.z = fmaf(wi[j], v0[j].z, a0.z); a0.w = fmaf(wi[j], v0[j].w, a0.w);
            a1.x = fmaf(wi[j], v1[j].x, a1.x); a1.y = fmaf(wi[j], v1[j].y, a1.y);
            a1.z = fmaf(wi[j], v1[j].z, a1.z); a1.w = fmaf(wi[j], v1[j].w, a1.w);
        }
    }
    for (; e < end; e++) {
        int sA = g_src[e];
        float wA = g_w[e];
        const float4* tA = (const float4*)(t + (size_t)sA * CNHID);
        float4 vA0 = tA[lane], vA1 = tA[32 + lane];
        a0.x = fmaf(wA, vA0.x, a0.x); a0.y = fmaf(wA, vA0.y, a0.y);
        a0.z = fmaf(wA, vA0.z, a0.z); a0.w = fmaf(wA, vA0.w, a0.w);
        a1.x = fmaf(wA, vA1.x, a1.x); a1.y = fmaf(wA, vA1.y, a1.y);
        a1.z = fmaf(wA, vA1.z, a1.z); a1.w = fmaf(wA, vA1.w, a1.w);
    }

    float v[8] = {fmaxf(a0.x, 0.f), fmaxf(a0.y, 0.f), fmaxf(a0.z, 0.f), fmaxf(a0.w, 0.f),
                  fmaxf(a1.x, 0.f), fmaxf(a1.y, 0.f), fmaxf(a1.z, 0.f), fmaxf(a1.w, 0.f)};
    __align__(8) __half hb[8], lb[8];
#pragma unroll
    for (int k = 0; k < 8; k++) split1(v[k], hb[k], lb[k]);
    size_t base = (size_t)warp * CNHID + 4 * lane;
    *(uint2*)&Oh[base]       = *(uint2*)&hb[0];
    *(uint2*)&Oh[base + 128] = *(uint2*)&hb[4];
    *(uint2*)&Ol[base]       = *(uint2*)&lb[0];
    *(uint2*)&Ol[base + 128] = *(uint2*)&lb[4];
}

// ---------------- log_softmax --------------------------------------------------
__global__ void k_logsoftmax64(float* __restrict__ out, int n) {
    int gt = blockIdx.x * blockDim.x + threadIdx.x;
    int warp = gt >> 5, lane = gt & 31;
    if (warp >= n) return;
    float* r = out + (size_t)warp * 64;
    float v0 = r[lane], v1 = r[lane + 32];
    float m = fmaxf(v0, v1);
#pragma unroll
    for (int o = 16; o; o >>= 1) m = fmaxf(m, __shfl_xor_sync(0xffffffffu, m, o));
    float s = expf(v0 - m) + expf(v1 - m);
#pragma unroll
    for (int o = 16; o; o >>= 1) s += __shfl_xor_sync(0xffffffffu, s, o);
    float l = m + logf(s);
    r[lane] = v0 - l;
    r[lane + 32] = v1 - l;
}

// ---------------- pre-split FP16 tensor-core GEMM (3-stage pipeline) -----------
__device__ __forceinline__ void mma_f16(float* c, const uint32_t* a, const uint32_t* b) {
    asm volatile(
        "mma.sync.aligned.m16n8k16.row.col.f32.f16.f16.f32 "
        "{%0,%1,%2,%3}, {%4,%5,%6,%7}, {%8,%9}, {%0,%1,%2,%3};\n"
        : "+f"(c[0]), "+f"(c[1]), "+f"(c[2]), "+f"(c[3])
        : "r"(a[0]), "r"(a[1]), "r"(a[2]), "r"(a[3]), "r"(b[0]), "r"(b[1]));
}
__device__ __forceinline__ void ldsm4(uint32_t& r0, uint32_t& r1, uint32_t& r2,
                                      uint32_t& r3, uint32_t addr) {
    asm volatile("ldmatrix.sync.aligned.m8n8.x4.shared.b16 {%0,%1,%2,%3}, [%4];"
                 : "=r"(r0), "=r"(r1), "=r"(r2), "=r"(r3) : "r"(addr));
}
__device__ __forceinline__ uint32_t s2u(const void* p) {
    uint32_t a;
    asm("{ .reg .u64 t; cvta.to.shared.u64 t, %1; cvt.u32.u64 %0, t; }" : "=r"(a) : "l"(p));
    return a;
}
__device__ __forceinline__ void cpa16(uint32_t dst, const void* src, bool pred) {
    asm volatile("cp.async.cg.shared.global [%0], [%1], 16, %2;"
                 :: "r"(dst), "l"(src), "r"(pred ? 16 : 0) : "memory");
}
__device__ __forceinline__ void cpa_commit() {
    asm volatile("cp.async.commit_group;" ::: "memory");
}
template <int NN>
__device__ __forceinline__ void cpa_wait() {
    asm volatile("cp.async.wait_group %0;" :: "n"(NN) : "memory");
}

// C[M,N] = A @ B; A (hi,lo) f16 [M][K]; B transposed (hi,lo) f16 [N][K].
// BM=128, BN=64, BK=32, 256 threads (8 warps: 4 m x 2 n), MT=2, 3-stage cp.async.
// EPI: 0 plain fp32 | 1 bias+ELU -> split (Oh,Ol) | 2 bias fp32
template <int EPI>
__global__ void __launch_bounds__(256, 2)
k_hgemm(const __half* __restrict__ Ah, const __half* __restrict__ Al,
        const __half* __restrict__ Bh, const __half* __restrict__ Bl,
        float* __restrict__ C, const float* __restrict__ bias,
        __half* __restrict__ Oh, __half* __restrict__ Ol,
        int M, int N, int K) {
    constexpr int BN     = 64;
    constexpr int RSTR   = 80;                 // 64B data + 16B pad
    constexpr int ATILE  = 128 * RSTR;         // 10240
    constexpr int ASTAGE = 2 * ATILE;          // hi+lo = 20480
    constexpr int BTILE  = BN * RSTR;          // 5120
    constexpr int BSTAGE = 2 * BTILE;          // 10240
    constexpr int OFFB   = 3 * ASTAGE;         // after 3 A stages
    constexpr int MT     = 2;

    extern __shared__ char smem[];
    const uint32_t sb = s2u(smem);
    const int tid = threadIdx.x;
    const int wid = tid >> 5, lane = tid & 31;
    const int grp = lane >> 2, qid = lane & 3;
    const int warp_m = wid >> 1, warp_n = wid & 1;
    const int row0 = blockIdx.y * 128;
    const int col0 = blockIdx.x * BN;

    const int lrow = lane & 15;
    const int lcol = (lane >> 4) * 16;

    float acc[MT][4][4];
#pragma unroll
    for (int i = 0; i < MT; i++)
#pragma unroll
        for (int j = 0; j < 4; j++)
#pragma unroll
            for (int c = 0; c < 4; c++) acc[i][j][c] = 0.0f;

    auto loadSlab = [&](int s, int b) {
        int k0 = s * 32;
#pragma unroll
        for (int i = 0; i < 2; i++) {
            int c = tid + i * 256;
            int r = c >> 2, p = c & 3;
            bool ok = (row0 + r) < M;
            int rr = ok ? (row0 + r) : (M - 1);
            size_t g = (size_t)rr * K + k0 + p * 8;
            uint32_t dst = sb + b * ASTAGE + r * RSTR + p * 16;
            cpa16(dst,         Ah + g, ok);
            cpa16(dst + ATILE, Al + g, ok);
        }
        {
            int r = tid >> 2, p = tid & 3;
            size_t g = (size_t)(col0 + r) * K + k0 + p * 8;
            uint32_t dst = sb + OFFB + b * BSTAGE + r * RSTR + p * 16;
            cpa16(dst,         Bh + g, true);
            cpa16(dst + BTILE, Bl + g, true);
        }
        cpa_commit();
    };

    auto computeSlab = [&](int b) {
        const uint32_t aB = sb + b * ASTAGE;
        const uint32_t bB = sb + OFFB + b * BSTAGE;
#pragma unroll
        for (int ks = 0; ks < 2; ks++) {
            const int kb = ks * 32 + lcol;
            uint32_t bh[4][2], bl[4][2];
#pragma unroll
            for (int p = 0; p < 2; p++) {
                uint32_t addr = bB + (warp_n * 32 + p * 16 + lrow) * RSTR + kb;
                ldsm4(bh[2 * p][0], bh[2 * p + 1][0], bh[2 * p][1], bh[2 * p + 1][1], addr);
                ldsm4(bl[2 * p][0], bl[2 * p + 1][0], bl[2 * p][1], bl[2 * p + 1][1],
                      addr + BTILE);
            }
#pragma unroll
            for (int mt = 0; mt < MT; mt++) {
                uint32_t addr = aB + (warp_m * (MT * 16) + mt * 16 + lrow) * RSTR + kb;
                uint32_t ah[4], al[4];
                ldsm4(ah[0], ah[1], ah[2], ah[3], addr);
                ldsm4(al[0], al[1], al[2], al[3], addr + ATILE);
#pragma unroll
                for (int nt = 0; nt < 4; nt++) {
                    mma_f16(acc[mt][nt], ah, bh[nt]);   // hi*hi
                    mma_f16(acc[mt][nt], ah, bl[nt]);   // hi*lo
                    mma_f16(acc[mt][nt], al, bh[nt]);   // lo*hi
                }
            }
        }
    };

    const int ns = K / 32;
    loadSlab(0, 0);
    if (ns > 1) loadSlab(1, 1);
    for (int s = 0; s < ns; s++) {
        int b = s % 3;
        if (s + 1 < ns) cpa_wait<1>(); else cpa_wait<0>();
        __syncthreads();
        if (s + 2 < ns) loadSlab(s + 2, (s + 2) % 3);
        computeSlab(b);
    }

    // ---- epilogue ----
#pragma unroll
    for (int mt = 0; mt < MT; mt++) {
        int rbase = row0 + warp_m * (MT * 16) + mt * 16 + grp;
#pragma unroll
        for (int nt = 0; nt < 4; nt++) {
            int cb = col0 + warp_n * 32 + nt * 8 + 2 * qid;
#pragma unroll
            for (int half = 0; half < 2; half++) {
                int r = rbase + half * 8;
                if (r >= M) continue;
                float v0 = acc[mt][nt][half * 2 + 0];
                float v1 = acc[mt][nt][half * 2 + 1];
                if (EPI >= 1) { v0 += bias[cb]; v1 += bias[cb + 1]; }
                if (EPI == 1) {
                    v0 = v0 > 0.0f ? v0 : expm1f(v0);
                    v1 = v1 > 0.0f ? v1 : expm1f(v1);
                    __half h0, l0, h1, l1;
                    split1(v0, h0, l0);
                    split1(v1, h1, l1);
                    size_t base = (size_t)r * N + cb;
                    *(__half2*)&Oh[base] = __halves2half2(h0, h1);
                    *(__half2*)&Ol[base] = __halves2half2(l0, l1);
                } else {
                    *(float2*)&C[(size_t)r * N + cb] = make_float2(v0, v1);
                }
            }
        }
    }
}

// ---------------- host orchestration ---------------------------------------
static inline int cdiv(long long a, long long b) { return (int)((a + b - 1) / b); }

extern "C" void kernel_launch(void* const* d_in, const int* in_sizes, int n_in,
                              void* d_out, int out_size) {
    const float* x    = (const float*)d_in[0];
    const int*   y    = (const int*)  d_in[1];
    const int*   adj  = (const int*)  d_in[3];
    const int*   idxl = (const int*)  d_in[4];
    const float* W0  = (const float*)d_in[6];
    const float* b0  = (const float*)d_in[7];
    const float* W1  = (const float*)d_in[8];
    const float* b1  = (const float*)d_in[9];
    const float* W2  = (const float*)d_in[10];
    const float* b2  = (const float*)d_in[11];
    const float* Wm0 = (const float*)d_in[12];
    const float* bm0 = (const float*)d_in[13];
    const float* Wm1 = (const float*)d_in[14];
    const float* bm1 = (const float*)d_in[15];

    int N = in_sizes[1];
    int E = in_sizes[3] / 2;
    int L = in_sizes[4];
    float* out = (float*)d_out;

    float* p_t;
    __half *p_hh, *p_hl, *p_mh, *p_ml, *p_xh, *p_xl;
    __half *w0h, *w0l, *w1h, *w1l, *w2h, *w2l, *wm0h, *wm0l, *wm1h, *wm1l;
    cudaGetSymbolAddress((void**)&p_t,  g_t);
    cudaGetSymbolAddress((void**)&p_hh, g_h_hi);
    cudaGetSymbolAddress((void**)&p_hl, g_h_lo);
    cudaGetSymbolAddress((void**)&p_mh, g_m_hi);
    cudaGetSymbolAddress((void**)&p_ml, g_m_lo);
    cudaGetSymbolAddress((void**)&p_xh, g_x_hi);
    cudaGetSymbolAddress((void**)&p_xl, g_x_lo);
    cudaGetSymbolAddress((void**)&w0h,  g_w0t_hi);  cudaGetSymbolAddress((void**)&w0l,  g_w0t_lo);
    cudaGetSymbolAddress((void**)&w1h,  g_w1t_hi);  cudaGetSymbolAddress((void**)&w1l,  g_w1t_lo);
    cudaGetSymbolAddress((void**)&w2h,  g_w2t_hi);  cudaGetSymbolAddress((void**)&w2l,  g_w2t_lo);
    cudaGetSymbolAddress((void**)&wm0h, g_wm0t_hi); cudaGetSymbolAddress((void**)&wm0l, g_wm0t_lo);
    cudaGetSymbolAddress((void**)&wm1h, g_wm1t_hi); cudaGetSymbolAddress((void**)&wm1l, g_wm1t_lo);

    const int TB = 256;
    const int SMEM = 3 * (2 * 128 * 80) + 3 * (2 * 64 * 80);   // 92160
    cudaFuncSetAttribute(k_hgemm<0>, cudaFuncAttributeMaxDynamicSharedMemorySize, SMEM);
    cudaFuncSetAttribute(k_hgemm<1>, cudaFuncAttributeMaxDynamicSharedMemorySize, SMEM);
    cudaFuncSetAttribute(k_hgemm<2>, cudaFuncAttributeMaxDynamicSharedMemorySize, SMEM);

    long long xq = (long long)N * CNFEAT / 4;
    long long nwcell = (long long)N * 32;
    int gy = cdiv(N, 128);

    // launches 1-3: prep needed by GEMM1
    k_split<<<cdiv(xq, TB), TB>>>(x, p_xh, p_xl, xq);
    k_wt<<<cdiv(256 * 512, TB), TB>>>(W0, w0h, w0l, 512, 256);
    k_wt<<<cdiv(256 * 256, TB), TB>>>(W1, w1h, w1l, 256, 256);

    // launch 4 (ncu-captured): GCN layer-1 GEMM
    k_hgemm<0><<<dim3(4, gy), 256, SMEM>>>(p_xh, p_xl, w0h, w0l,
                                           p_t, nullptr, nullptr, nullptr,
                                           N, 256, 512);

    // remaining prep
    k_wt<<<cdiv(256 * 256, TB), TB>>>(W2, w2h, w2l, 256, 256);
    k_wt<<<cdiv(512 * 256, TB), TB>>>(Wm0, wm0h, wm0l, 256, 512);
    k_wt<<<cdiv(64 * 512, TB), TB>>>(Wm1, wm1h, wm1l, 512, 64);
    k_lab_init<<<cdiv(N, TB), TB>>>(N);
    k_lab_set<<<cdiv(L, TB), TB>>>(idxl, y, L);
    k_zero_cnt<<<cdiv(N, TB), TB>>>(N);
    k_count<<<cdiv(E, TB), TB>>>(adj, E);
    k_scan<<<1, 1024>>>(N, E);
    k_dinv<<<cdiv(N, TB), TB>>>(N);
    k_fill<<<cdiv(E, TB), TB>>>(adj, E);

    // layer 1 finish
    k_lab_add<<<cdiv(nwcell, TB), TB>>>(W0, N);
    k_agg_csr<<<cdiv(nwcell, TB), TB>>>(p_t, p_hh, p_hl, b0, N);

    // GCN layer 2
    k_hgemm<0><<<dim3(4, gy), 256, SMEM>>>(p_hh, p_hl, w1h, w1l,
                                           p_t, nullptr, nullptr, nullptr,
                                           N, 256, 256);
    k_agg_csr<<<cdiv(nwcell, TB), TB>>>(p_t, p_hh, p_hl, b1, N);

    // GCN layer 3
    k_hgemm<0><<<dim3(4, gy), 256, SMEM>>>(p_hh, p_hl, w2h, w2l,
                                           p_t, nullptr, nullptr, nullptr,
                                           N, 256, 256);
    k_agg_csr<<<cdiv(nwcell, TB), TB>>>(p_t, p_hh, p_hl, b2, N);

    // MLP head
    k_hgemm<1><<<dim3(8, gy), 256, SMEM>>>(p_hh, p_hl, wm0h, wm0l,
                                           nullptr, bm0, p_mh, p_ml,
                                           N, 512, 256);
    k_hgemm<2><<<dim3(1, gy), 256, SMEM>>>(p_mh, p_ml, wm1h, wm1l,
                                           out, bm1, nullptr, nullptr,
                                           N, 64, 512);

    // log_softmax
    k_logsoftmax64<<<cdiv(nwcell, TB), TB>>>(out, N);
}

// round 12
// speedup vs baseline: 1.0767x; 1.0767x over previous
#include <cuda_runtime.h>
#include <cuda_fp16.h>
#include <cstdint>
#include <math.h>

// Problem constants (fixed shapes)
#define CN      100000
#define CE      1600000
#define CNFEAT  512
#define CNLABEL 64
#define CNHID   256
#define CHID2   512

// ---------------- scratch (device globals) ----------------------------------
__device__ float  g_t   [(size_t)CN * CNHID];
__device__ __half g_h_hi[(size_t)CN * CNHID];
__device__ __half g_h_lo[(size_t)CN * CNHID];
__device__ __half g_m_hi[(size_t)CN * CHID2];
__device__ __half g_m_lo[(size_t)CN * CHID2];
__device__ __half g_x_hi[(size_t)CN * CNFEAT];
__device__ __half g_x_lo[(size_t)CN * CNFEAT];
__device__ __half g_w0t_hi[256 * 512], g_w0t_lo[256 * 512];
__device__ __half g_w1t_hi[256 * 256], g_w1t_lo[256 * 256];
__device__ __half g_w2t_hi[256 * 256], g_w2t_lo[256 * 256];
__device__ __half g_wm0t_hi[512 * 256], g_wm0t_lo[512 * 256];
__device__ __half g_wm1t_hi[64 * 512],  g_wm1t_lo[64 * 512];
__device__ float  g_dinv[CN];
__device__ int    g_cnt[CN];
__device__ int    g_rowptr[CN + 1];
__device__ int    g_cursor[CN];
__device__ int    g_src[CE];
__device__ float  g_w[CE];
__device__ int    g_lab[CN];

// ---------------- CSR build --------------------------------------------------
__global__ void k_zero_cnt(int n) {
    int i = blockIdx.x * blockDim.x + threadIdx.x;
    if (i < n) g_cnt[i] = 0;
}
__global__ void k_count(const int* __restrict__ adj, int E) {
    int e = blockIdx.x * blockDim.x + threadIdx.x;
    if (e >= E) return;
    atomicAdd(&g_cnt[adj[E + e]], 1);
}
__global__ void k_scan(int n, int E) {
    __shared__ int bs[1024];
    int tid = threadIdx.x;
    int chunk = (n + 1023) / 1024;
    int lo = tid * chunk;
    int hi = lo + chunk; if (hi > n) hi = n; if (lo > n) lo = n;
    int s = 0;
    for (int i = lo; i < hi; i++) s += g_cnt[i];
    int mysum = s;
    bs[tid] = s;
    __syncthreads();
    for (int d = 1; d < 1024; d <<= 1) {
        int v = (tid >= d) ? bs[tid - d] : 0;
        __syncthreads();
        bs[tid] += v;
        __syncthreads();
    }
    int off = bs[tid] - mysum;
    for (int i = lo; i < hi; i++) {
        g_rowptr[i] = off;
        g_cursor[i] = off;
        off += g_cnt[i];
    }
    if (tid == 1023) g_rowptr[n] = E;
}
__global__ void k_dinv(int n) {
    int i = blockIdx.x * blockDim.x + threadIdx.x;
    if (i < n) g_dinv[i] = rsqrtf((float)g_cnt[i] + 2.0f);
}
__global__ void k_fill(const int* __restrict__ adj, int E) {
    int e = blockIdx.x * blockDim.x + threadIdx.x;
    if (e >= E) return;
    int src = adj[e];
    int dst = adj[E + e];
    int pos = atomicAdd(&g_cursor[dst], 1);
    g_src[pos] = src;
    g_w[pos] = g_dinv[src] * g_dinv[dst];
}

// ---------------- labels ------------------------------------------------------
__global__ void k_lab_init(int n) {
    int i = blockIdx.x * blockDim.x + threadIdx.x;
    if (i < n) g_lab[i] = -1;
}
__global__ void k_lab_set(const int* __restrict__ idxl, const int* __restrict__ y, int L) {
    int t = blockIdx.x * blockDim.x + threadIdx.x;
    if (t >= L) return;
    int node = idxl[t];
    g_lab[node] = y[node];
}
__global__ void k_lab_add(const float* __restrict__ W0, int n) {
    int gt = blockIdx.x * blockDim.x + threadIdx.x;
    int warp = gt >> 5, lane = gt & 31;
    if (warp >= n) return;
    int lab = g_lab[warp];
    if (lab < 0) return;
    const float* wrow = W0 + (size_t)(CNFEAT + lab) * CNHID;
    float* trow = g_t + (size_t)warp * CNHID;
#pragma unroll
    for (int k = 0; k < CNHID / 32; k++)
        trow[k * 32 + lane] += wrow[k * 32 + lane];
}

// ---------------- split helpers ------------------------------------------------
__device__ __forceinline__ void split1(float v, __half& h, __half& l) {
    h = __float2half_rn(v);
    l = __float2half_rn(v - __half2float(h));
}

__global__ void k_split(const float* __restrict__ X, __half* __restrict__ H,
                        __half* __restrict__ L, long long nq) {
    long long i = (long long)blockIdx.x * blockDim.x + threadIdx.x;
    if (i >= nq) return;
    float4 v = ((const float4*)X)[i];
    __half2 h0 = __floats2half2_rn(v.x, v.y), h1 = __floats2half2_rn(v.z, v.w);
    float2 f0 = __half22float2(h0), f1 = __half22float2(h1);
    __half2 l0 = __floats2half2_rn(v.x - f0.x, v.y - f0.y);
    __half2 l1 = __floats2half2_rn(v.z - f1.x, v.w - f1.y);
    ((__half2*)H)[2 * i] = h0; ((__half2*)H)[2 * i + 1] = h1;
    ((__half2*)L)[2 * i] = l0; ((__half2*)L)[2 * i + 1] = l1;
}

__global__ void k_wt(const float* __restrict__ W, __half* __restrict__ TH,
                     __half* __restrict__ TL, int K, int N) {
    int idx = blockIdx.x * blockDim.x + threadIdx.x;
    if (idx >= N * K) return;
    int n = idx / K, k = idx % K;
    float v = W[(size_t)k * N + n];
    __half h, l;
    split1(v, h, l);
    TH[idx] = h;
    TL[idx] = l;
}

// ---------------- fused CSR aggregation --------------------------------------
__global__ void __launch_bounds__(256)
k_agg_csr(const float* __restrict__ t, __half* __restrict__ Oh, __half* __restrict__ Ol,
          const float* __restrict__ bias, int n) {
    int warp = (blockIdx.x * blockDim.x + threadIdx.x) >> 5;
    int lane = threadIdx.x & 31;
    if (warp >= n) return;
    int beg = g_rowptr[warp];
    int end = g_rowptr[warp + 1];
    const float4* ti = (const float4*)(t + (size_t)warp * CNHID);
    const float4* bi = (const float4*)bias;
    float d = g_dinv[warp];
    float sw = 2.0f * d * d;

    float4 a0 = bi[lane], a1 = bi[32 + lane];
    float4 s0 = ti[lane], s1 = ti[32 + lane];
    a0.x += sw * s0.x; a0.y += sw * s0.y; a0.z += sw * s0.z; a0.w += sw * s0.w;
    a1.x += sw * s1.x; a1.y += sw * s1.y; a1.z += sw * s1.z; a1.w += sw * s1.w;

    int e = beg;
    for (; e + 1 < end; e += 2) {
        int sA = g_src[e], sB = g_src[e + 1];
        float wA = g_w[e], wB = g_w[e + 1];
        const float4* tA = (const float4*)(t + (size_t)sA * CNHID);
        const float4* tB = (const float4*)(t + (size_t)sB * CNHID);
        float4 vA0 = tA[lane], vA1 = tA[32 + lane];
        float4 vB0 = tB[lane], vB1 = tB[32 + lane];
        a0.x = fmaf(wA, vA0.x, a0.x); a0.y = fmaf(wA, vA0.y, a0.y);
        a0.z = fmaf(wA, vA0.z, a0.z); a0.w = fmaf(wA, vA0.w, a0.w);
        a1.x = fmaf(wA, vA1.x, a1.x); a1.y = fmaf(wA, vA1.y, a1.y);
        a1.z = fmaf(wA, vA1.z, a1.z); a1.w = fmaf(wA, vA1.w, a1.w);
        a0.x = fmaf(wB, vB0.x, a0.x); a0.y = fmaf(wB, vB0.y, a0.y);
        a0.z = fmaf(wB, vB0.z, a0.z); a0.w = fmaf(wB, vB0.w, a0.w);
        a1.x = fmaf(wB, vB1.x, a1.x); a1.y = fmaf(wB, vB1.y, a1.y);
        a1.z = fmaf(wB, vB1.z, a1.z); a1.w = fmaf(wB, vB1.w, a1.w);
    }
    if (e < end) {
        int sA = g_src[e];
        float wA = g_w[e];
        const float4* tA = (const float4*)(t + (size_t)sA * CNHID);
        float4 vA0 = tA[lane], vA1 = tA[32 + lane];
        a0.x = fmaf(wA, vA0.x, a0.x); a0.y = fmaf(wA, vA0.y, a0.y);
        a0.z = fmaf(wA, vA0.z, a0.z); a0.w = fmaf(wA, vA0.w, a0.w);
        a1.x = fmaf(wA, vA1.x, a1.x); a1.y = fmaf(wA, vA1.y, a1.y);
        a1.z = fmaf(wA, vA1.z, a1.z); a1.w = fmaf(wA, vA1.w, a1.w);
    }

    float v[8] = {fmaxf(a0.x, 0.f), fmaxf(a0.y, 0.f), fmaxf(a0.z, 0.f), fmaxf(a0.w, 0.f),
                  fmaxf(a1.x, 0.f), fmaxf(a1.y, 0.f), fmaxf(a1.z, 0.f), fmaxf(a1.w, 0.f)};
    __align__(8) __half hb[8], lb[8];
#pragma unroll
    for (int k = 0; k < 8; k++) split1(v[k], hb[k], lb[k]);
    size_t base = (size_t)warp * CNHID + 4 * lane;
    *(uint2*)&Oh[base]       = *(uint2*)&hb[0];
    *(uint2*)&Oh[base + 128] = *(uint2*)&hb[4];
    *(uint2*)&Ol[base]       = *(uint2*)&lb[0];
    *(uint2*)&Ol[base + 128] = *(uint2*)&lb[4];
}

// ---------------- log_softmax --------------------------------------------------
__global__ void k_logsoftmax64(float* __restrict__ out, int n) {
    int gt = blockIdx.x * blockDim.x + threadIdx.x;
    int warp = gt >> 5, lane = gt & 31;
    if (warp >= n) return;
    float* r = out + (size_t)warp * 64;
    float v0 = r[lane], v1 = r[lane + 32];
    float m = fmaxf(v0, v1);
#pragma unroll
    for (int o = 16; o; o >>= 1) m = fmaxf(m, __shfl_xor_sync(0xffffffffu, m, o));
    float s = expf(v0 - m) + expf(v1 - m);
#pragma unroll
    for (int o = 16; o; o >>= 1) s += __shfl_xor_sync(0xffffffffu, s, o);
    float l = m + logf(s);
    r[lane] = v0 - l;
    r[lane + 32] = v1 - l;
}

// ---------------- pre-split FP16 tensor-core GEMM (R7 config) ------------------
__device__ __forceinline__ void mma_f16(float* c, const uint32_t* a, const uint32_t* b) {
    asm volatile(
        "mma.sync.aligned.m16n8k16.row.col.f32.f16.f16.f32 "
        "{%0,%1,%2,%3}, {%4,%5,%6,%7}, {%8,%9}, {%0,%1,%2,%3};\n"
        : "+f"(c[0]), "+f"(c[1]), "+f"(c[2]), "+f"(c[3])
        : "r"(a[0]), "r"(a[1]), "r"(a[2]), "r"(a[3]), "r"(b[0]), "r"(b[1]));
}
__device__ __forceinline__ void ldsm4(uint32_t& r0, uint32_t& r1, uint32_t& r2,
                                      uint32_t& r3, uint32_t addr) {
    asm volatile("ldmatrix.sync.aligned.m8n8.x4.shared.b16 {%0,%1,%2,%3}, [%4];"
                 : "=r"(r0), "=r"(r1), "=r"(r2), "=r"(r3) : "r"(addr));
}
__device__ __forceinline__ uint32_t s2u(const void* p) {
    uint32_t a;
    asm("{ .reg .u64 t; cvta.to.shared.u64 t, %1; cvt.u32.u64 %0, t; }" : "=r"(a) : "l"(p));
    return a;
}
__device__ __forceinline__ void cpa16(uint32_t dst, const void* src, bool pred) {
    asm volatile("cp.async.cg.shared.global [%0], [%1], 16, %2;"
                 :: "r"(dst), "l"(src), "r"(pred ? 16 : 0) : "memory");
}
__device__ __forceinline__ void cpa_commit() {
    asm volatile("cp.async.commit_group;" ::: "memory");
}
__device__ __forceinline__ void cpa_wait0() {
    asm volatile("cp.async.wait_group 0;" ::: "memory");
}

// C[M,N] = A @ B; A (hi,lo) f16 [M][K]; B transposed (hi,lo) f16 [N][K].
// BM=128, BK=32. EPI: 0 plain fp32 | 1 bias+ELU -> split (Oh,Ol) | 2 bias fp32
template <int BN, int EPI>
__global__ void __launch_bounds__(256)
k_hgemm(const __half* __restrict__ Ah, const __half* __restrict__ Al,
        const __half* __restrict__ Bh, const __half* __restrict__ Bl,
        float* __restrict__ C, const float* __restrict__ bias,
        __half* __restrict__ Oh, __half* __restrict__ Ol,
        int M, int N, int K) {
    constexpr int RSTR  = 80;                 // 64B data + 16B pad
    constexpr int ATILE = 128 * RSTR;
    constexpr int ABUF  = 2 * ATILE;
    constexpr int BTILE = BN * RSTR;
    constexpr int BBUF  = 2 * BTILE;
    constexpr int OFFB  = 2 * ABUF;
    constexpr int NWN   = BN / 32;
    constexpr int MT    = (128 / (8 / NWN)) / 16;

    extern __shared__ char smem[];
    const uint32_t sb = s2u(smem);
    const int tid = threadIdx.x;
    const int wid = tid >> 5, lane = tid & 31;
    const int grp = lane >> 2, qid = lane & 3;
    const int warp_m = wid / NWN, warp_n = wid % NWN;
    const int row0 = blockIdx.y * 128;
    const int col0 = blockIdx.x * BN;

    const int lrow = lane & 15;
    const int lcol = (lane >> 4) * 16;

    float acc[MT][4][4];
#pragma unroll
    for (int i = 0; i < MT; i++)
#pragma unroll
        for (int j = 0; j < 4; j++)
#pragma unroll
            for (int c = 0; c < 4; c++) acc[i][j][c] = 0.0f;

    auto loadSlab = [&](int s, int b) {
        int k0 = s * 32;
#pragma unroll
        for (int i = 0; i < 2; i++) {
            int c = tid + i * 256;
            int r = c >> 2, p = c & 3;
            bool ok = (row0 + r) < M;
            int rr = ok ? (row0 + r) : (M - 1);
            size_t g = (size_t)rr * K + k0 + p * 8;
            uint32_t dst = sb + b * ABUF + r * RSTR + p * 16;
            cpa16(dst,         Ah + g, ok);
            cpa16(dst + ATILE, Al + g, ok);
        }
#pragma unroll
        for (int i = 0; i < BN / 64; i++) {
            int c = tid + i * 256;
            int r = c >> 2, p = c & 3;
            size_t g = (size_t)(col0 + r) * K + k0 + p * 8;
            uint32_t dst = sb + OFFB + b * BBUF + r * RSTR + p * 16;
            cpa16(dst,         Bh + g, true);
            cpa16(dst + BTILE, Bl + g, true);
        }
        cpa_commit();
    };

    auto computeSlab = [&](int b) {
        const uint32_t aB = sb + b * ABUF;
        const uint32_t bB = sb + OFFB + b * BBUF;
#pragma unroll
        for (int ks = 0; ks < 2; ks++) {
            const int kb = ks * 32 + lcol;
            uint32_t bh[4][2], bl[4][2];
#pragma unroll
            for (int p = 0; p < 2; p++) {
                uint32_t addr = bB + (warp_n * 32 + p * 16 + lrow) * RSTR + kb;
                ldsm4(bh[2 * p][0], bh[2 * p + 1][0], bh[2 * p][1], bh[2 * p + 1][1], addr);
                ldsm4(bl[2 * p][0], bl[2 * p + 1][0], bl[2 * p][1], bl[2 * p + 1][1],
                      addr + BTILE);
            }
#pragma unroll
            for (int mt = 0; mt < MT; mt++) {
                uint32_t addr = aB + (warp_m * (MT * 16) + mt * 16 + lrow) * RSTR + kb;
                uint32_t ah[4], al[4];
                ldsm4(ah[0], ah[1], ah[2], ah[3], addr);
                ldsm4(al[0], al[1], al[2], al[3], addr + ATILE);
#pragma unroll
                for (int nt = 0; nt < 4; nt++) {
                    mma_f16(acc[mt][nt], ah, bh[nt]);   // hi*hi
                    mma_f16(acc[mt][nt], ah, bl[nt]);   // hi*lo
                    mma_f16(acc[mt][nt], al, bh[nt]);   // lo*hi
                }
            }
        }
    };

    const int ns = K / 32;
    loadSlab(0, 0);
    cpa_wait0();
    __syncthreads();
    for (int s = 0; s < ns; s++) {
        int b = s & 1;
        if (s + 1 < ns) loadSlab(s + 1, b ^ 1);
        computeSlab(b);
        if (s + 1 < ns) {
            cpa_wait0();
            __syncthreads();
        }
    }

    // ---- epilogue ----
#pragma unroll
    for (int mt = 0; mt < MT; mt++) {
        int rbase = row0 + warp_m * (MT * 16) + mt * 16 + grp;
#pragma unroll
        for (int nt = 0; nt < 4; nt++) {
            int cb = col0 + warp_n * 32 + nt * 8 + 2 * qid;
#pragma unroll
            for (int half = 0; half < 2; half++) {
                int r = rbase + half * 8;
                if (r >= M) continue;
                float v0 = acc[mt][nt][half * 2 + 0];
                float v1 = acc[mt][nt][half * 2 + 1];
                if (EPI >= 1) { v0 += bias[cb]; v1 += bias[cb + 1]; }
                if (EPI == 1) {
                    v0 = v0 > 0.0f ? v0 : expm1f(v0);
                    v1 = v1 > 0.0f ? v1 : expm1f(v1);
                    __half h0, l0, h1, l1;
                    split1(v0, h0, l0);
                    split1(v1, h1, l1);
                    size_t base = (size_t)r * N + cb;
                    *(__half2*)&Oh[base] = __halves2half2(h0, h1);
                    *(__half2*)&Ol[base] = __halves2half2(l0, l1);
                } else {
                    *(float2*)&C[(size_t)r * N + cb] = make_float2(v0, v1);
                }
            }
        }
    }
}

// ---------------- host orchestration ---------------------------------------
static inline int cdiv(long long a, long long b) { return (int)((a + b - 1) / b); }

extern "C" void kernel_launch(void* const* d_in, const int* in_sizes, int n_in,
                              void* d_out, int out_size) {
    const float* x    = (const float*)d_in[0];
    const int*   y    = (const int*)  d_in[1];
    const int*   adj  = (const int*)  d_in[3];
    const int*   idxl = (const int*)  d_in[4];
    const float* W0  = (const float*)d_in[6];
    const float* b0  = (const float*)d_in[7];
    const float* W1  = (const float*)d_in[8];
    const float* b1  = (const float*)d_in[9];
    const float* W2  = (const float*)d_in[10];
    const float* b2  = (const float*)d_in[11];
    const float* Wm0 = (const float*)d_in[12];
    const float* bm0 = (const float*)d_in[13];
    const float* Wm1 = (const float*)d_in[14];
    const float* bm1 = (const float*)d_in[15];

    int N = in_sizes[1];
    int E = in_sizes[3] / 2;
    int L = in_sizes[4];
    float* out = (float*)d_out;

    float* p_t;
    __half *p_hh, *p_hl, *p_mh, *p_ml, *p_xh, *p_xl;
    __half *w0h, *w0l, *w1h, *w1l, *w2h, *w2l, *wm0h, *wm0l, *wm1h, *wm1l;
    cudaGetSymbolAddress((void**)&p_t,  g_t);
    cudaGetSymbolAddress((void**)&p_hh, g_h_hi);
    cudaGetSymbolAddress((void**)&p_hl, g_h_lo);
    cudaGetSymbolAddress((void**)&p_mh, g_m_hi);
    cudaGetSymbolAddress((void**)&p_ml, g_m_lo);
    cudaGetSymbolAddress((void**)&p_xh, g_x_hi);
    cudaGetSymbolAddress((void**)&p_xl, g_x_lo);
    cudaGetSymbolAddress((void**)&w0h,  g_w0t_hi);  cudaGetSymbolAddress((void**)&w0l,  g_w0t_lo);
    cudaGetSymbolAddress((void**)&w1h,  g_w1t_hi);  cudaGetSymbolAddress((void**)&w1l,  g_w1t_lo);
    cudaGetSymbolAddress((void**)&w2h,  g_w2t_hi);  cudaGetSymbolAddress((void**)&w2l,  g_w2t_lo);
    cudaGetSymbolAddress((void**)&wm0h, g_wm0t_hi); cudaGetSymbolAddress((void**)&wm0l, g_wm0t_lo);
    cudaGetSymbolAddress((void**)&wm1h, g_wm1t_hi); cudaGetSymbolAddress((void**)&wm1l, g_wm1t_lo);

    // lazy one-time stream/event creation (outside capture on the correctness call)
    static cudaStream_t s1 = nullptr;
    static cudaEvent_t evFork = nullptr, evJoin = nullptr;
    if (s1 == nullptr) {
        cudaStreamCreateWithFlags(&s1, cudaStreamNonBlocking);
        cudaEventCreateWithFlags(&evFork, cudaEventDisableTiming);
        cudaEventCreateWithFlags(&evJoin, cudaEventDisableTiming);
    }

    const int TB = 256;
    const int SMEM128 = 2 * 2 * 128 * 80 + 2 * 2 * 128 * 80;   // 81920
    const int SMEM64  = 2 * 2 * 128 * 80 + 2 * 2 * 64 * 80;    // 61440
    cudaFuncSetAttribute(k_hgemm<128, 0>, cudaFuncAttributeMaxDynamicSharedMemorySize, SMEM128);
    cudaFuncSetAttribute(k_hgemm<128, 1>, cudaFuncAttributeMaxDynamicSharedMemorySize, SMEM128);
    cudaFuncSetAttribute(k_hgemm<64, 2>,  cudaFuncAttributeMaxDynamicSharedMemorySize, SMEM64);

    long long xq = (long long)N * CNFEAT / 4;
    long long nwcell = (long long)N * 32;
    int gy = cdiv(N, 128);

    // ---- fork: prep branch on s1 runs concurrently with split/wt0/GEMM1 ----
    cudaEventRecord(evFork, 0);
    cudaStreamWaitEvent(s1, evFork, 0);

    // stream 0: GEMM1 dependency chain
    k_split<<<cdiv(xq, TB), TB>>>(x, p_xh, p_xl, xq);
    k_wt<<<cdiv(256 * 512, TB), TB>>>(W0, w0h, w0l, 512, 256);
    k_hgemm<128, 0><<<dim3(2, gy), 256, SMEM128>>>(p_xh, p_xl, w0h, w0l,
                                                   p_t, nullptr, nullptr, nullptr,
                                                   N, 256, 512);

    // stream s1: everything independent of GEMM1
    k_wt<<<cdiv(256 * 256, TB), TB, 0, s1>>>(W1, w1h, w1l, 256, 256);
    k_wt<<<cdiv(256 * 256, TB), TB, 0, s1>>>(W2, w2h, w2l, 256, 256);
    k_wt<<<cdiv(512 * 256, TB), TB, 0, s1>>>(Wm0, wm0h, wm0l, 256, 512);
    k_wt<<<cdiv(64 * 512, TB), TB, 0, s1>>>(Wm1, wm1h, wm1l, 512, 64);
    k_lab_init<<<cdiv(N, TB), TB, 0, s1>>>(N);
    k_lab_set<<<cdiv(L, TB), TB, 0, s1>>>(idxl, y, L);
    k_zero_cnt<<<cdiv(N, TB), TB, 0, s1>>>(N);
    k_count<<<cdiv(E, TB), TB, 0, s1>>>(adj, E);
    k_scan<<<1, 1024, 0, s1>>>(N, E);
    k_dinv<<<cdiv(N, TB), TB, 0, s1>>>(N);
    k_fill<<<cdiv(E, TB), TB, 0, s1>>>(adj, E);

    // ---- join ----
    cudaEventRecord(evJoin, s1);
    cudaStreamWaitEvent(0, evJoin, 0);

    // layer 1 finish
    k_lab_add<<<cdiv(nwcell, TB), TB>>>(W0, N);
    k_agg_csr<<<cdiv(nwcell, TB), TB>>>(p_t, p_hh, p_hl, b0, N);

    // GCN layer 2
    k_hgemm<128, 0><<<dim3(2, gy), 256, SMEM128>>>(p_hh, p_hl, w1h, w1l,
                                                   p_t, nullptr, nullptr, nullptr,
                                                   N, 256, 256);
    k_agg_csr<<<cdiv(nwcell, TB), TB>>>(p_t, p_hh, p_hl, b1, N);

    // GCN layer 3
    k_hgemm<128, 0><<<dim3(2, gy), 256, SMEM128>>>(p_hh, p_hl, w2h, w2l,
                                                   p_t, nullptr, nullptr, nullptr,
                                                   N, 256, 256);
    k_agg_csr<<<cdiv(nwcell, TB), TB>>>(p_t, p_hh, p_hl, b2, N);

    // MLP head
    k_hgemm<128, 1><<<dim3(4, gy), 256, SMEM128>>>(p_hh, p_hl, wm0h, wm0l,
                                                   nullptr, bm0, p_mh, p_ml,
                                                   N, 512, 256);
    k_hgemm<64, 2><<<dim3(1, gy), 256, SMEM64>>>(p_mh, p_ml, wm1h, wm1l,
                                                 out, bm1, nullptr, nullptr,
                                                 N, 64, 512);

    // log_softmax
    k_logsoftmax64<<<cdiv(nwcell, TB), TB>>>(out, N);
}